// round 15
// baseline (speedup 1.0000x reference)
#include <cuda_runtime.h>

// NutritionLoss: Gaussian soft-lookup over NF=1000 foods is numerically a
// one-hot for integer ids (off-weight exp(-100) ~ 3.7e-44) -> hard gather.
//
//   loss = 5 * mean_b sum_c | sum_{d,m,s} (data[pid,c]*pamt - data[tid,c]*tamt) / 700 |
//
// R12 -> R13: one warp = one batch (64 blocks x 32 threads, 14 slots/thread).
// Deletes ALL cross-warp plumbing: no smem, no __syncthreads, no 14-way
// serial fold, no second shuffle stage. Warp reduction via REDUX
// (__reduce_add_sync) on 2^9 fixed-point ints: 1 instr/category instead of
// a 5-level shuffle tree, and bitwise-deterministic. Tail keeps the packed
// single-atomic (counter@bit56 + fixed-point sum in one word, zero fences).

#define NF 1000
#define NC 5
#define ELEMS 448          // D*M*S = 7*4*16
#define BATCH 64
#define SLOTS_PER_LANE 14  // 448 / 32

#define FP_SCALE 512.0f    // 2^9: 32 lanes * 14 slots * 5000 * 512 = 1.15e9 < 2^31
#define CNT_ONE  (1ULL << 56)
#define SUM_MASK (CNT_ONE - 1ULL)

__device__ unsigned long long d_acc = 0ULL;  // [63:56]=arrivals, [55:0]=fixed-point sum

__global__ __launch_bounds__(32) void nl_main(
    const float* __restrict__ y_pred,   // [B,D,M,S,2] interleaved (id, amt)
    const float* __restrict__ y,        // [B,D,M,S,2]
    const float* __restrict__ data,     // [NF,NC]
    float* __restrict__ out)            // scalar
{
    const int lane = threadIdx.x;
    const int b = blockIdx.x;

    const float2* __restrict__ ypv = reinterpret_cast<const float2*>(y_pred) + b * ELEMS;
    const float2* __restrict__ ytv = reinterpret_cast<const float2*>(y)      + b * ELEMS;

    // Preload all 28 input pairs (coalesced, all LDGs in flight together).
    float2 p[SLOTS_PER_LANE], q[SLOTS_PER_LANE];
    #pragma unroll
    for (int i = 0; i < SLOTS_PER_LANE; i++) {
        p[i] = ypv[i * 32 + lane];
        q[i] = ytv[i * 32 + lane];
    }

    // Gather + accumulate: 280 independent table LDGs per warp (L2-hot 20KB
    // table), FFMA chains per category are short (14 deep) and hidden.
    float facc[NC] = {0.f, 0.f, 0.f, 0.f, 0.f};
    #pragma unroll
    for (int i = 0; i < SLOTS_PER_LANE; i++) {
        const int pid = __float2int_rn(p[i].x);   // matches jnp.round (no .5 cases)
        const int tid = __float2int_rn(q[i].x);   // true ids are exact integers
        const float pamt = p[i].y;
        const float tamt = q[i].y;
        #pragma unroll
        for (int c = 0; c < NC; c++)
            facc[c] = fmaf(__ldg(&data[pid * NC + c]), pamt,
                      fmaf(-__ldg(&data[tid * NC + c]), tamt, facc[c]));
    }

    // Fixed-point REDUX across the warp: one instruction per category.
    const unsigned full = 0xffffffffu;
    unsigned long long tot = 0ULL;
    #pragma unroll
    for (int c = 0; c < NC; c++) {
        int s = __reduce_add_sync(full, __float2int_rn(facc[c] * FP_SCALE));
        tot += (unsigned long long)(s < 0 ? -s : s);   // |per-batch category sum|
    }

    // Packed single-atomic tail: data + arrival counter in one word, no fences.
    if (lane == 0) {
        unsigned long long payload = tot | CNT_ONE;
        unsigned long long prev = atomicAdd(&d_acc, payload);
        if ((prev >> 56) == (BATCH - 1)) {
            unsigned long long total_fx = (prev + payload) & SUM_MASK;
            atomicExch(&d_acc, 0ULL);     // self-reset for next graph replay
            // * 1/FP_SCALE, * (1/700) elementwise, * (1/B) mean, * 5 penalty
            out[0] = (float)total_fx * (5.0f / (FP_SCALE * 700.0f * (float)BATCH));
        }
    }
}

extern "C" void kernel_launch(void* const* d_in, const int* in_sizes, int n_in,
                              void* d_out, int out_size) {
    const float* y_pred = (const float*)d_in[0];
    const float* y      = (const float*)d_in[1];
    const float* data   = (const float*)d_in[2];
    float* out = (float*)d_out;

    nl_main<<<BATCH, 32>>>(y_pred, y, data, out);
}